// round 2
// baseline (speedup 1.0000x reference)
#include <cuda_runtime.h>
#include <cuda_bf16.h>

// Problem constants
#define NB    4
#define SEQ   2048
#define DIN   768
#define DOUT  768
#define NH    12
#define DHD   64
#define MROWS (NB * SEQ)   // 8192

// Scratch (global device arrays; no runtime allocation allowed)
__device__ float g_Q[(size_t)NB * NH * SEQ * DHD];   // [b,h,s,dh]
__device__ float g_K[(size_t)NB * NH * SEQ * DHD];
__device__ float g_V[(size_t)NB * NH * SEQ * DHD];
__device__ float g_ctx[(size_t)MROWS * DOUT];        // [b*s, h*dh] row-major

// ---------------------------------------------------------------------------
// QKV projection: Y = X @ W for W in {Wq,Wk,Wv} (blockIdx.z selects),
// output stored permuted to [b, h, s, dh].
// 128x128 block tile, BK=16, 8x8 per-thread microtile, 256 threads.
// ---------------------------------------------------------------------------
__global__ __launch_bounds__(256, 2)
void gemm_qkv_kernel(const float* __restrict__ X,
                     const float* __restrict__ Wq,
                     const float* __restrict__ Wk,
                     const float* __restrict__ Wv) {
    __shared__ float As[16][128];   // A transposed: As[k][m]
    __shared__ float Bs[16][128];   // Bs[k][n]

    const float* W   = (blockIdx.z == 0) ? Wq : (blockIdx.z == 1) ? Wk : Wv;
    float*       Out = (blockIdx.z == 0) ? g_Q : (blockIdx.z == 1) ? g_K : g_V;

    const int tid = threadIdx.x;
    const int m0  = blockIdx.y * 128;
    const int n0  = blockIdx.x * 128;
    const int ty  = tid >> 4, tx = tid & 15;

    float acc[8][8];
#pragma unroll
    for (int r = 0; r < 8; r++)
#pragma unroll
        for (int c = 0; c < 8; c++) acc[r][c] = 0.f;

    for (int k0 = 0; k0 < DIN; k0 += 16) {
#pragma unroll
        for (int i = 0; i < 2; i++) {
            const int f   = tid + i * 256;
            const int ar  = f >> 2, akc = (f & 3) * 4;
            float4 av = *(const float4*)(X + (size_t)(m0 + ar) * DIN + k0 + akc);
            As[akc + 0][ar] = av.x;
            As[akc + 1][ar] = av.y;
            As[akc + 2][ar] = av.z;
            As[akc + 3][ar] = av.w;
            const int br  = f >> 5, bnc = (f & 31) * 4;
            float4 bv = *(const float4*)(W + (size_t)(k0 + br) * DOUT + n0 + bnc);
            *(float4*)&Bs[br][bnc] = bv;
        }
        __syncthreads();
#pragma unroll
        for (int kk = 0; kk < 16; kk++) {
            float a[8], b[8];
            *(float4*)&a[0] = *(const float4*)&As[kk][ty * 8];
            *(float4*)&a[4] = *(const float4*)&As[kk][ty * 8 + 4];
            *(float4*)&b[0] = *(const float4*)&Bs[kk][tx * 8];
            *(float4*)&b[4] = *(const float4*)&Bs[kk][tx * 8 + 4];
#pragma unroll
            for (int r = 0; r < 8; r++)
#pragma unroll
                for (int c = 0; c < 8; c++)
                    acc[r][c] = fmaf(a[r], b[c], acc[r][c]);
        }
        __syncthreads();
    }

    // Permuted store: (m, n) -> [b, h, s, dh]
#pragma unroll
    for (int r = 0; r < 8; r++) {
        const int m  = m0 + ty * 8 + r;
        const int bb = m >> 11;            // m / SEQ
        const int s  = m & 2047;           // m % SEQ
#pragma unroll
        for (int c = 0; c < 8; c++) {
            const int n  = n0 + tx * 8 + c;
            const int h  = n >> 6;
            const int dh = n & 63;
            Out[(((size_t)bb * NH + h) * SEQ + s) * DHD + dh] = acc[r][c];
        }
    }
}

// ---------------------------------------------------------------------------
// Causal flash attention. One block per (q_tile of 64, b*h).
// 64x64 key tiles, online softmax, 4x4 per-thread score/output microtile.
// P tile aliases the K smem tile. Writes ctx as [b*s, h*64+dh].
// Qs/Ks padded to 65 (row-strided reads); Vs unpadded (broadcast reads).
// ---------------------------------------------------------------------------
__global__ __launch_bounds__(256)
void attn_kernel() {
    extern __shared__ float sm[];
    float* Qs = sm;                         // [64][65]
    float* Ks = sm + 64 * 65;               // [64][65] — aliased by P later
    float* Vs = sm + 2 * 64 * 65;           // [64][64]

    const int qt = blockIdx.x;
    const int bh = blockIdx.y;
    const int b  = bh / NH;
    const int h  = bh - b * NH;

    const float* Qg = g_Q + ((size_t)bh * SEQ + qt * 64) * DHD;
    const float* Kg = g_K + (size_t)bh * SEQ * DHD;
    const float* Vg = g_V + (size_t)bh * SEQ * DHD;

    const int tid = threadIdx.x;
    const int ty  = tid >> 4, tx = tid & 15;

    // Load Q tile once
    for (int i = tid; i < 64 * 64; i += 256) {
        const int r = i >> 6, c = i & 63;
        Qs[r * 65 + c] = Qg[r * 64 + c];
    }

    float o[4][4];
    float mrow[4], lrow[4];
#pragma unroll
    for (int r = 0; r < 4; r++) {
        mrow[r] = -3.0e38f;
        lrow[r] = 0.f;
#pragma unroll
        for (int c = 0; c < 4; c++) o[r][c] = 0.f;
    }

    for (int kt = 0; kt <= qt; kt++) {
        __syncthreads();  // previous-iter readers of Ks/Vs done
        for (int i = tid; i < 64 * 64; i += 256) {
            const int r = i >> 6, c = i & 63;
            Ks[r * 65 + c] = Kg[((size_t)kt * 64 + r) * 64 + c];
            Vs[r * 64 + c] = Vg[((size_t)kt * 64 + r) * 64 + c];
        }
        __syncthreads();

        // Scores: S = Q K^T * scale
        float s[4][4];
#pragma unroll
        for (int r = 0; r < 4; r++)
#pragma unroll
            for (int c = 0; c < 4; c++) s[r][c] = 0.f;

#pragma unroll 8
        for (int d = 0; d < 64; d++) {
            float qr[4], kc[4];
#pragma unroll
            for (int r = 0; r < 4; r++) qr[r] = Qs[(ty * 4 + r) * 65 + d];
#pragma unroll
            for (int c = 0; c < 4; c++) kc[c] = Ks[(tx * 4 + c) * 65 + d];
#pragma unroll
            for (int r = 0; r < 4; r++)
#pragma unroll
                for (int c = 0; c < 4; c++)
                    s[r][c] = fmaf(qr[r], kc[c], s[r][c]);
        }

        const float scale = 0.125f;  // 1/sqrt(64)
        if (kt == qt) {
#pragma unroll
            for (int r = 0; r < 4; r++)
#pragma unroll
                for (int c = 0; c < 4; c++)
                    s[r][c] = (tx * 4 + c > ty * 4 + r) ? -3.0e38f
                                                        : s[r][c] * scale;
        } else {
#pragma unroll
            for (int r = 0; r < 4; r++)
#pragma unroll
                for (int c = 0; c < 4; c++) s[r][c] *= scale;
        }

        // Online softmax update (row owned by the 16 lanes sharing ty)
        float p[4][4];
#pragma unroll
        for (int r = 0; r < 4; r++) {
            float mx = fmaxf(fmaxf(s[r][0], s[r][1]), fmaxf(s[r][2], s[r][3]));
#pragma unroll
            for (int off = 8; off > 0; off >>= 1)
                mx = fmaxf(mx, __shfl_xor_sync(0xffffffffu, mx, off));
            const float newm = fmaxf(mrow[r], mx);
            float sum = 0.f;
#pragma unroll
            for (int c = 0; c < 4; c++) {
                p[r][c] = __expf(s[r][c] - newm);
                sum += p[r][c];
            }
#pragma unroll
            for (int off = 8; off > 0; off >>= 1)
                sum += __shfl_xor_sync(0xffffffffu, sum, off);
            const float alpha = __expf(mrow[r] - newm);
            lrow[r] = lrow[r] * alpha + sum;
            mrow[r] = newm;
#pragma unroll
            for (int c = 0; c < 4; c++) o[r][c] *= alpha;
        }

        __syncthreads();  // done reading Ks as scores input
        // P -> smem (aliases Ks)
#pragma unroll
        for (int r = 0; r < 4; r++)
#pragma unroll
            for (int c = 0; c < 4; c++)
                Ks[(ty * 4 + r) * 65 + tx * 4 + c] = p[r][c];
        __syncthreads();

        // O += P @ V
#pragma unroll 8
        for (int k = 0; k < 64; k++) {
            float pr[4], vc[4];
#pragma unroll
            for (int r = 0; r < 4; r++) pr[r] = Ks[(ty * 4 + r) * 65 + k];
#pragma unroll
            for (int c = 0; c < 4; c++) vc[c] = Vs[k * 64 + tx * 4 + c];
#pragma unroll
            for (int r = 0; r < 4; r++)
#pragma unroll
                for (int c = 0; c < 4; c++)
                    o[r][c] = fmaf(pr[r], vc[c], o[r][c]);
        }
    }

    // Epilogue: normalize and store ctx as [b*s, h*64 + dh]
#pragma unroll
    for (int r = 0; r < 4; r++) {
        const float inv = 1.f / lrow[r];
        const int q = qt * 64 + ty * 4 + r;
        const size_t base = ((size_t)b * SEQ + q) * DOUT + h * 64 + tx * 4;
#pragma unroll
        for (int c = 0; c < 4; c++)
            g_ctx[base + c] = o[r][c] * inv;
    }
}

// ---------------------------------------------------------------------------
// Output projection: out = ctx @ Wo + bo. Same tiling as QKV GEMM.
// ---------------------------------------------------------------------------
__global__ __launch_bounds__(256, 2)
void gemm_out_kernel(const float* __restrict__ Wo,
                     const float* __restrict__ bo,
                     float* __restrict__ Out) {
    __shared__ float As[16][128];
    __shared__ float Bs[16][128];

    const int tid = threadIdx.x;
    const int m0  = blockIdx.y * 128;
    const int n0  = blockIdx.x * 128;
    const int ty  = tid >> 4, tx = tid & 15;

    float acc[8][8];
#pragma unroll
    for (int r = 0; r < 8; r++)
#pragma unroll
        for (int c = 0; c < 8; c++) acc[r][c] = 0.f;

    for (int k0 = 0; k0 < DOUT; k0 += 16) {
#pragma unroll
        for (int i = 0; i < 2; i++) {
            const int f   = tid + i * 256;
            const int ar  = f >> 2, akc = (f & 3) * 4;
            float4 av = *(const float4*)(g_ctx + (size_t)(m0 + ar) * DOUT + k0 + akc);
            As[akc + 0][ar] = av.x;
            As[akc + 1][ar] = av.y;
            As[akc + 2][ar] = av.z;
            As[akc + 3][ar] = av.w;
            const int br  = f >> 5, bnc = (f & 31) * 4;
            float4 bv = *(const float4*)(Wo + (size_t)(k0 + br) * DOUT + n0 + bnc);
            *(float4*)&Bs[br][bnc] = bv;
        }
        __syncthreads();
#pragma unroll
        for (int kk = 0; kk < 16; kk++) {
            float a[8], b[8];
            *(float4*)&a[0] = *(const float4*)&As[kk][ty * 8];
            *(float4*)&a[4] = *(const float4*)&As[kk][ty * 8 + 4];
            *(float4*)&b[0] = *(const float4*)&Bs[kk][tx * 8];
            *(float4*)&b[4] = *(const float4*)&Bs[kk][tx * 8 + 4];
#pragma unroll
            for (int r = 0; r < 8; r++)
#pragma unroll
                for (int c = 0; c < 8; c++)
                    acc[r][c] = fmaf(a[r], b[c], acc[r][c]);
        }
        __syncthreads();
    }

#pragma unroll
    for (int r = 0; r < 8; r++) {
        const int m = m0 + ty * 8 + r;
#pragma unroll
        for (int c = 0; c < 8; c++) {
            const int n = n0 + tx * 8 + c;
            Out[(size_t)m * DOUT + n] = acc[r][c] + bo[n];
        }
    }
}

// ---------------------------------------------------------------------------
// Launch. Inputs per metadata order:
// [0]=input_tensor f32 [4,2048,768], [1]=mask bool (unused; causal is known),
// [2]=Wq, [3]=Wk, [4]=Wv, [5]=Wo, [6]=bo. Output f32 [4,2048,768].
// ---------------------------------------------------------------------------
extern "C" void kernel_launch(void* const* d_in, const int* in_sizes, int n_in,
                              void* d_out, int out_size) {
    const float* x  = (const float*)d_in[0];
    const float* Wq = (const float*)d_in[2];
    const float* Wk = (const float*)d_in[3];
    const float* Wv = (const float*)d_in[4];
    const float* Wo = (const float*)d_in[5];
    const float* bo = (const float*)d_in[6];
    float* out = (float*)d_out;

    // QKV projections (z selects Wq/Wk/Wv)
    dim3 gq(DOUT / 128, MROWS / 128, 3);
    gemm_qkv_kernel<<<gq, 256>>>(x, Wq, Wk, Wv);

    // Flash attention (dynamic smem: 2*64*65 + 64*64 floats = 49664 B)
    const int smem_bytes = (2 * 64 * 65 + 64 * 64) * (int)sizeof(float);
    cudaFuncSetAttribute(attn_kernel,
                         cudaFuncAttributeMaxDynamicSharedMemorySize,
                         smem_bytes);
    attn_kernel<<<dim3(SEQ / 64, NB * NH), 256, smem_bytes>>>();

    // Output projection + bias
    gemm_out_kernel<<<dim3(DOUT / 128, MROWS / 128), 256>>>(Wo, bo, out);
}

// round 5
// speedup vs baseline: 1.4012x; 1.4012x over previous
#include <cuda_runtime.h>
#include <cuda_bf16.h>
#include <cstdint>

// Problem constants
#define NB    4
#define SEQ   2048
#define DIN   768
#define DOUT  768
#define NH    12
#define DHD   64
#define MROWS (NB * SEQ)   // 8192
#define NTOT  2304         // Wq|Wk|Wv concatenated N
#define KC    32
#define NCH   (DIN / KC)   // 24

// ---------------------------------------------------------------------------
// Scratch (global device arrays; no runtime allocation allowed)
// ---------------------------------------------------------------------------
__device__ float g_Q[(size_t)NB * NH * SEQ * DHD];   // [b,h,s,dh]
__device__ float g_K[(size_t)NB * NH * SEQ * DHD];
__device__ float g_V[(size_t)NB * NH * SEQ * DHD];
__device__ float g_ctx[(size_t)MROWS * DOUT];        // [b*s, h*dh]

__device__ __align__(16) __nv_bfloat16 g_Xhi[(size_t)MROWS * DIN];
__device__ __align__(16) __nv_bfloat16 g_Xlo[(size_t)MROWS * DIN];
__device__ __align__(16) __nv_bfloat16 g_Chi[(size_t)MROWS * DOUT];
__device__ __align__(16) __nv_bfloat16 g_Clo[(size_t)MROWS * DOUT];
// Transposed weights [N,K] K-major: rows 0..2303 = Wq^T|Wk^T|Wv^T, 2304..3071 = Wo^T
__device__ __align__(16) __nv_bfloat16 g_Wthi[(size_t)(NTOT + DOUT) * DIN];
__device__ __align__(16) __nv_bfloat16 g_Wtlo[(size_t)(NTOT + DOUT) * DIN];

// ---------------------------------------------------------------------------
// PTX helpers (all sm_80+ portable: cp.async, ldmatrix, mma.sync)
// ---------------------------------------------------------------------------
__device__ __forceinline__ uint32_t smem_u32(const void* p) {
    uint32_t a;
    asm("{ .reg .u64 t; cvta.to.shared.u64 t, %1; cvt.u32.u64 %0, t; }"
        : "=r"(a) : "l"(p));
    return a;
}
__device__ __forceinline__ void cp16(uint32_t dst, const void* src) {
    asm volatile("cp.async.cg.shared.global [%0], [%1], 16;"
                 :: "r"(dst), "l"(src));
}
#define CP_COMMIT() asm volatile("cp.async.commit_group;" ::: "memory")
#define CP_WAIT(n)  asm volatile("cp.async.wait_group %0;" :: "n"(n) : "memory")

__device__ __forceinline__ void ldm_x4(uint32_t* r, uint32_t a) {
    asm volatile("ldmatrix.sync.aligned.m8n8.x4.shared.b16 {%0,%1,%2,%3}, [%4];"
                 : "=r"(r[0]), "=r"(r[1]), "=r"(r[2]), "=r"(r[3]) : "r"(a));
}
__device__ __forceinline__ void mma16816(float* d, const uint32_t* a,
                                         const uint32_t* b) {
    asm volatile(
        "mma.sync.aligned.m16n8k16.row.col.f32.bf16.bf16.f32 "
        "{%0,%1,%2,%3}, {%4,%5,%6,%7}, {%8,%9}, {%0,%1,%2,%3};"
        : "+f"(d[0]), "+f"(d[1]), "+f"(d[2]), "+f"(d[3])
        : "r"(a[0]), "r"(a[1]), "r"(a[2]), "r"(a[3]), "r"(b[0]), "r"(b[1]));
}

// smem: 2 stages x 4 arrays (Ahi,Alo,Bhi,Blo), each 128 rows x 80 B (pad 40 bf16)
#define ROW_B    80
#define ARR_B    (128 * ROW_B)          // 10240 B
#define STAGE_B  (4 * ARR_B)            // 40960 B
#define GEMM_SMEM (2 * STAGE_B)         // 81920 B

// ---------------------------------------------------------------------------
// hi/lo split conversion. DST=0: x -> g_Xhi/g_Xlo. DST=1: g_ctx -> g_Chi/g_Clo.
// ---------------------------------------------------------------------------
template <int DST>
__global__ void cvt_split_kernel(const float* __restrict__ src, int n4) {
    int i = blockIdx.x * blockDim.x + threadIdx.x;
    if (i >= n4) return;
    __nv_bfloat16* hi = (DST == 0) ? g_Xhi : g_Chi;
    __nv_bfloat16* lo = (DST == 0) ? g_Xlo : g_Clo;
    float4 v = ((const float4*)src)[i];
    __nv_bfloat16 h0 = __float2bfloat16(v.x);
    __nv_bfloat16 h1 = __float2bfloat16(v.y);
    __nv_bfloat16 h2 = __float2bfloat16(v.z);
    __nv_bfloat16 h3 = __float2bfloat16(v.w);
    ushort4 hv, lv;
    hv.x = *(unsigned short*)&h0; hv.y = *(unsigned short*)&h1;
    hv.z = *(unsigned short*)&h2; hv.w = *(unsigned short*)&h3;
    __nv_bfloat16 l0 = __float2bfloat16(v.x - __bfloat162float(h0));
    __nv_bfloat16 l1 = __float2bfloat16(v.y - __bfloat162float(h1));
    __nv_bfloat16 l2 = __float2bfloat16(v.z - __bfloat162float(h2));
    __nv_bfloat16 l3 = __float2bfloat16(v.w - __bfloat162float(h3));
    lv.x = *(unsigned short*)&l0; lv.y = *(unsigned short*)&l1;
    lv.z = *(unsigned short*)&l2; lv.w = *(unsigned short*)&l3;
    ((ushort4*)hi)[i] = hv;
    ((ushort4*)lo)[i] = lv;
}

// ---------------------------------------------------------------------------
// Weight transpose + hi/lo split: W[K,N] -> Wt[N,K] (bf16 hi/lo)
// ---------------------------------------------------------------------------
__global__ void cvt_w_kernel(const float* __restrict__ Wq, const float* __restrict__ Wk,
                             const float* __restrict__ Wv, const float* __restrict__ Wo) {
    __shared__ float t[32][33];
    const int z = blockIdx.z;
    const float* W = (z == 0) ? Wq : (z == 1) ? Wk : (z == 2) ? Wv : Wo;
    const int rowoff = (z < 3) ? z * DOUT : NTOT;
    const int k0 = blockIdx.y * 32, n0 = blockIdx.x * 32;
    const int tx = threadIdx.x, ty = threadIdx.y;
#pragma unroll
    for (int i = 0; i < 4; i++)
        t[ty + i * 8][tx] = W[(size_t)(k0 + ty + i * 8) * DOUT + n0 + tx];
    __syncthreads();
#pragma unroll
    for (int i = 0; i < 4; i++) {
        const int r = ty + i * 8;
        const float x = t[tx][r];
        const __nv_bfloat16 h = __float2bfloat16(x);
        const float res = x - __bfloat162float(h);
        const size_t di = (size_t)(rowoff + n0 + r) * DIN + k0 + tx;
        g_Wthi[di] = h;
        g_Wtlo[di] = __float2bfloat16(res);
    }
}

// ---------------------------------------------------------------------------
// bf16x3 HMMA GEMM: D[128x128] fp32 = Ahi*Bhi + Ahi*Blo + Alo*Bhi over K=768.
// 8 warps, warp tile 64x32 (4 m16 frags x 4 n8 frags), cp.async double buffer.
// EPI 0: permuted store -> g_Q/g_K/g_V (A = g_Xhi/lo, B = Wt rows 0..2303).
// EPI 1: plain store + bias -> Out     (A = g_Chi/lo, B = Wt rows 2304..3071).
// ---------------------------------------------------------------------------
template <int EPI>
__global__ __launch_bounds__(256, 1)
void mma_gemm_kernel(const float* __restrict__ bias, float* __restrict__ OutPlain) {
    extern __shared__ char smc[];
    const uint32_t smb = smem_u32(smc);
    const int tid = threadIdx.x, wid = tid >> 5, lane = tid & 31;
    const int warp_m = wid & 1, warp_n = wid >> 1;
    const int m0 = blockIdx.y * 128, n0 = blockIdx.x * 128;

    const __nv_bfloat16* Ahi = (EPI == 0) ? g_Xhi : g_Chi;
    const __nv_bfloat16* Alo = (EPI == 0) ? g_Xlo : g_Clo;
    const __nv_bfloat16* Bhi = (EPI == 0) ? g_Wthi : (g_Wthi + (size_t)NTOT * DIN);
    const __nv_bfloat16* Blo = (EPI == 0) ? g_Wtlo : (g_Wtlo + (size_t)NTOT * DIN);

    float acc[4][4][4];
#pragma unroll
    for (int mf = 0; mf < 4; mf++)
#pragma unroll
        for (int nf = 0; nf < 4; nf++)
#pragma unroll
            for (int j = 0; j < 4; j++) acc[mf][nf][j] = 0.f;

    auto load_chunk = [&](int ch, int st) {
#pragma unroll
        for (int t = 0; t < 4; t++) {
            const __nv_bfloat16* s = (t == 0) ? Ahi : (t == 1) ? Alo
                                   : (t == 2) ? Bhi : Blo;
            const int rb = (t < 2) ? m0 : n0;
            const uint32_t base = smb + (uint32_t)(st * STAGE_B + t * ARR_B);
#pragma unroll
            for (int j = 0; j < 2; j++) {
                const int id = tid + j * 256;       // 0..511 16B chunks
                const int row = id >> 2, c = id & 3;
                cp16(base + row * ROW_B + c * 16,
                     s + (size_t)(rb + row) * DIN + ch * KC + c * 8);
            }
        }
        CP_COMMIT();
    };

    load_chunk(0, 0);

    for (int ch = 0; ch < NCH; ch++) {
        const int st = ch & 1;
        if (ch + 1 < NCH) {
            load_chunk(ch + 1, st ^ 1);
            CP_WAIT(1);
        } else {
            CP_WAIT(0);
        }
        __syncthreads();

        const uint32_t sA = smb + st * STAGE_B;
        const uint32_t sB = sA + 2 * ARR_B;

#pragma unroll
        for (int k16 = 0; k16 < 2; k16++) {
            uint32_t ah[4][4], al[4][4], bh[4][2], bl[4][2];
#pragma unroll
            for (int f = 0; f < 4; f++) {
                const uint32_t addr = sA +
                    (warp_m * 64 + f * 16 + (lane & 15)) * ROW_B +
                    k16 * 32 + ((lane >> 4) << 4);
                ldm_x4(ah[f], addr);
                ldm_x4(al[f], addr + ARR_B);
            }
#pragma unroll
            for (int g = 0; g < 2; g++) {
                uint32_t rh[4], rl[4];
                const uint32_t addr = sB +
                    (warp_n * 32 + g * 16 + (lane & 7) + ((lane >> 4) << 3)) * ROW_B +
                    k16 * 32 + (((lane >> 3) & 1) << 4);
                ldm_x4(rh, addr);
                ldm_x4(rl, addr + ARR_B);
                bh[g * 2][0] = rh[0]; bh[g * 2][1] = rh[1];
                bh[g * 2 + 1][0] = rh[2]; bh[g * 2 + 1][1] = rh[3];
                bl[g * 2][0] = rl[0]; bl[g * 2][1] = rl[1];
                bl[g * 2 + 1][0] = rl[2]; bl[g * 2 + 1][1] = rl[3];
            }
#pragma unroll
            for (int mf = 0; mf < 4; mf++)
#pragma unroll
                for (int nf = 0; nf < 4; nf++) {
                    mma16816(acc[mf][nf], ah[mf], bh[nf]);
                    mma16816(acc[mf][nf], ah[mf], bl[nf]);
                    mma16816(acc[mf][nf], al[mf], bh[nf]);
                }
        }
        __syncthreads();   // protect this stage before next-next load overwrites
    }

    // Epilogue straight from registers.
    // Thread (mf,nf): d0,d1 = (row=lane/4, col=(lane%4)*2 + {0,1}); d2,d3 = row+8.
#pragma unroll
    for (int mf = 0; mf < 4; mf++)
#pragma unroll
        for (int nf = 0; nf < 4; nf++) {
            const int m  = m0 + warp_m * 64 + mf * 16 + (lane >> 2);
            const int nl = warp_n * 32 + nf * 8 + (lane & 3) * 2;
            if (EPI == 0) {
                const int mat = blockIdx.x / (DOUT / 128);
                const int n = (blockIdx.x % (DOUT / 128)) * 128 + nl;
                float* Out = (mat == 0) ? g_Q : (mat == 1) ? g_K : g_V;
                const int h = n >> 6, dh = n & 63;
                const int b = m >> 11, s = m & 2047;
                float2 v0 = make_float2(acc[mf][nf][0], acc[mf][nf][1]);
                float2 v1 = make_float2(acc[mf][nf][2], acc[mf][nf][3]);
                *(float2*)&Out[(((size_t)b * NH + h) * SEQ + s) * DHD + dh] = v0;
                *(float2*)&Out[(((size_t)b * NH + h) * SEQ + (s + 8)) * DHD + dh] = v1;
            } else {
                const int n = n0 + nl;
                float2 v0 = make_float2(acc[mf][nf][0] + bias[n],
                                        acc[mf][nf][1] + bias[n + 1]);
                float2 v1 = make_float2(acc[mf][nf][2] + bias[n],
                                        acc[mf][nf][3] + bias[n + 1]);
                *(float2*)&OutPlain[(size_t)m * DOUT + n] = v0;
                *(float2*)&OutPlain[(size_t)(m + 8) * DOUT + n] = v1;
            }
        }
}

// ---------------------------------------------------------------------------
// Causal flash attention (unchanged from passing round-2 baseline).
// ---------------------------------------------------------------------------
__global__ __launch_bounds__(256)
void attn_kernel() {
    extern __shared__ float smf[];
    float* Qs = smf;
    float* Ks = smf + 64 * 65;
    float* Vs = smf + 2 * 64 * 65;

    const int qt = blockIdx.x;
    const int bh = blockIdx.y;
    const int b  = bh / NH;
    const int h  = bh - b * NH;

    const float* Qg = g_Q + ((size_t)bh * SEQ + qt * 64) * DHD;
    const float* Kg = g_K + (size_t)bh * SEQ * DHD;
    const float* Vg = g_V + (size_t)bh * SEQ * DHD;

    const int tid = threadIdx.x;
    const int ty  = tid >> 4, tx = tid & 15;

    for (int i = tid; i < 64 * 64; i += 256) {
        const int r = i >> 6, c = i & 63;
        Qs[r * 65 + c] = Qg[r * 64 + c];
    }

    float o[4][4], mrow[4], lrow[4];
#pragma unroll
    for (int r = 0; r < 4; r++) {
        mrow[r] = -3.0e38f; lrow[r] = 0.f;
#pragma unroll
        for (int c = 0; c < 4; c++) o[r][c] = 0.f;
    }

    for (int kt = 0; kt <= qt; kt++) {
        __syncthreads();
        for (int i = tid; i < 64 * 64; i += 256) {
            const int r = i >> 6, c = i & 63;
            Ks[r * 65 + c] = Kg[((size_t)kt * 64 + r) * 64 + c];
            Vs[r * 64 + c] = Vg[((size_t)kt * 64 + r) * 64 + c];
        }
        __syncthreads();

        float s[4][4];
#pragma unroll
        for (int r = 0; r < 4; r++)
#pragma unroll
            for (int c = 0; c < 4; c++) s[r][c] = 0.f;

#pragma unroll 8
        for (int d = 0; d < 64; d++) {
            float qr[4], kc[4];
#pragma unroll
            for (int r = 0; r < 4; r++) qr[r] = Qs[(ty * 4 + r) * 65 + d];
#pragma unroll
            for (int c = 0; c < 4; c++) kc[c] = Ks[(tx * 4 + c) * 65 + d];
#pragma unroll
            for (int r = 0; r < 4; r++)
#pragma unroll
                for (int c = 0; c < 4; c++)
                    s[r][c] = fmaf(qr[r], kc[c], s[r][c]);
        }

        const float scale = 0.125f;
        if (kt == qt) {
#pragma unroll
            for (int r = 0; r < 4; r++)
#pragma unroll
                for (int c = 0; c < 4; c++)
                    s[r][c] = (tx * 4 + c > ty * 4 + r) ? -3.0e38f : s[r][c] * scale;
        } else {
#pragma unroll
            for (int r = 0; r < 4; r++)
#pragma unroll
                for (int c = 0; c < 4; c++) s[r][c] *= scale;
        }

        float p[4][4];
#pragma unroll
        for (int r = 0; r < 4; r++) {
            float mx = fmaxf(fmaxf(s[r][0], s[r][1]), fmaxf(s[r][2], s[r][3]));
#pragma unroll
            for (int off = 8; off > 0; off >>= 1)
                mx = fmaxf(mx, __shfl_xor_sync(0xffffffffu, mx, off));
            const float newm = fmaxf(mrow[r], mx);
            float sum = 0.f;
#pragma unroll
            for (int c = 0; c < 4; c++) {
                p[r][c] = __expf(s[r][c] - newm);
                sum += p[r][c];
            }
#pragma unroll
            for (int off = 8; off > 0; off >>= 1)
                sum += __shfl_xor_sync(0xffffffffu, sum, off);
            const float alpha = __expf(mrow[r] - newm);
            lrow[r] = lrow[r] * alpha + sum;
            mrow[r] = newm;
#pragma unroll
            for (int c = 0; c < 4; c++) o[r][c] *= alpha;
        }

        __syncthreads();
#pragma unroll
        for (int r = 0; r < 4; r++)
#pragma unroll
            for (int c = 0; c < 4; c++)
                Ks[(ty * 4 + r) * 65 + tx * 4 + c] = p[r][c];
        __syncthreads();

#pragma unroll 8
        for (int k = 0; k < 64; k++) {
            float pr[4], vc[4];
#pragma unroll
            for (int r = 0; r < 4; r++) pr[r] = Ks[(ty * 4 + r) * 65 + k];
#pragma unroll
            for (int c = 0; c < 4; c++) vc[c] = Vs[k * 64 + tx * 4 + c];
#pragma unroll
            for (int r = 0; r < 4; r++)
#pragma unroll
                for (int c = 0; c < 4; c++)
                    o[r][c] = fmaf(pr[r], vc[c], o[r][c]);
        }
    }

#pragma unroll
    for (int r = 0; r < 4; r++) {
        const float inv = 1.f / lrow[r];
        const int q = qt * 64 + ty * 4 + r;
        const size_t base = ((size_t)b * SEQ + q) * DOUT + h * 64 + tx * 4;
#pragma unroll
        for (int c = 0; c < 4; c++)
            g_ctx[base + c] = o[r][c] * inv;
    }
}

// ---------------------------------------------------------------------------
// Launch. Inputs: [0]=x f32, [1]=mask (unused), [2..5]=Wq,Wk,Wv,Wo, [6]=bo.
// ---------------------------------------------------------------------------
extern "C" void kernel_launch(void* const* d_in, const int* in_sizes, int n_in,
                              void* d_out, int out_size) {
    const float* x  = (const float*)d_in[0];
    const float* Wq = (const float*)d_in[2];
    const float* Wk = (const float*)d_in[3];
    const float* Wv = (const float*)d_in[4];
    const float* Wo = (const float*)d_in[5];
    const float* bo = (const float*)d_in[6];
    float* out = (float*)d_out;

    cudaFuncSetAttribute(mma_gemm_kernel<0>,
                         cudaFuncAttributeMaxDynamicSharedMemorySize, GEMM_SMEM);
    cudaFuncSetAttribute(mma_gemm_kernel<1>,
                         cudaFuncAttributeMaxDynamicSharedMemorySize, GEMM_SMEM);

    // 1) Split X into hi/lo bf16
    const int n4x = MROWS * DIN / 4;
    cvt_split_kernel<0><<<(n4x + 255) / 256, 256>>>(x, n4x);
    // 2) Transpose + split all weights
    cvt_w_kernel<<<dim3(DOUT / 32, DIN / 32, 4), dim3(32, 8)>>>(Wq, Wk, Wv, Wo);

    // 3) Fused QKV GEMM (N = 2304), permuted epilogue
    mma_gemm_kernel<0><<<dim3(NTOT / 128, MROWS / 128), 256, GEMM_SMEM>>>(
        nullptr, nullptr);

    // 4) Flash attention
    const int attn_smem = (2 * 64 * 65 + 64 * 64) * (int)sizeof(float);
    cudaFuncSetAttribute(attn_kernel,
                         cudaFuncAttributeMaxDynamicSharedMemorySize, attn_smem);
    attn_kernel<<<dim3(SEQ / 64, NB * NH), 256, attn_smem>>>();

    // 5) Split ctx into hi/lo
    const int n4c = MROWS * DOUT / 4;
    float* gctx_ptr;
    cudaGetSymbolAddress((void**)&gctx_ptr, g_ctx);
    cvt_split_kernel<1><<<(n4c + 255) / 256, 256>>>(gctx_ptr, n4c);

    // 6) Output projection + bias
    mma_gemm_kernel<1><<<dim3(DOUT / 128, MROWS / 128), 256, GEMM_SMEM>>>(bo, out);
}

// round 7
// speedup vs baseline: 2.5998x; 1.8555x over previous
#include <cuda_runtime.h>
#include <cuda_bf16.h>
#include <cstdint>

// Problem constants
#define NB    4
#define SEQ   2048
#define DIN   768
#define DOUT  768
#define NH    12
#define DHD   64
#define MROWS (NB * SEQ)   // 8192
#define NTOT  2304         // Wq|Wk|Wv concatenated N
#define KC    32
#define NCH   (DIN / KC)   // 24

// ---------------------------------------------------------------------------
// Scratch (global device arrays; no runtime allocation allowed)
// ---------------------------------------------------------------------------
__device__ __align__(16) __nv_bfloat16 g_Qhi[(size_t)NB * NH * SEQ * DHD];
__device__ __align__(16) __nv_bfloat16 g_Qlo[(size_t)NB * NH * SEQ * DHD];
__device__ __align__(16) __nv_bfloat16 g_Khi[(size_t)NB * NH * SEQ * DHD];
__device__ __align__(16) __nv_bfloat16 g_Klo[(size_t)NB * NH * SEQ * DHD];
__device__ __align__(16) __nv_bfloat16 g_Vhi[(size_t)NB * NH * SEQ * DHD];
__device__ __align__(16) __nv_bfloat16 g_Vlo[(size_t)NB * NH * SEQ * DHD];

__device__ __align__(16) __nv_bfloat16 g_Xhi[(size_t)MROWS * DIN];
__device__ __align__(16) __nv_bfloat16 g_Xlo[(size_t)MROWS * DIN];
__device__ __align__(16) __nv_bfloat16 g_Chi[(size_t)MROWS * DOUT];
__device__ __align__(16) __nv_bfloat16 g_Clo[(size_t)MROWS * DOUT];
// Transposed weights [N,K] K-major: rows 0..2303 = Wq^T|Wk^T|Wv^T, 2304..3071 = Wo^T
__device__ __align__(16) __nv_bfloat16 g_Wthi[(size_t)(NTOT + DOUT) * DIN];
__device__ __align__(16) __nv_bfloat16 g_Wtlo[(size_t)(NTOT + DOUT) * DIN];

// ---------------------------------------------------------------------------
// PTX helpers (sm_80+ portable: cp.async, ldmatrix, mma.sync)
// ---------------------------------------------------------------------------
__device__ __forceinline__ uint32_t smem_u32(const void* p) {
    uint32_t a;
    asm("{ .reg .u64 t; cvta.to.shared.u64 t, %1; cvt.u32.u64 %0, t; }"
        : "=r"(a) : "l"(p));
    return a;
}
__device__ __forceinline__ void cp16(uint32_t dst, const void* src) {
    asm volatile("cp.async.cg.shared.global [%0], [%1], 16;"
                 :: "r"(dst), "l"(src));
}
#define CP_COMMIT() asm volatile("cp.async.commit_group;" ::: "memory")
#define CP_WAIT(n)  asm volatile("cp.async.wait_group %0;" :: "n"(n) : "memory")

__device__ __forceinline__ void ldm_x4(uint32_t* r, uint32_t a) {
    asm volatile("ldmatrix.sync.aligned.m8n8.x4.shared.b16 {%0,%1,%2,%3}, [%4];"
                 : "=r"(r[0]), "=r"(r[1]), "=r"(r[2]), "=r"(r[3]) : "r"(a));
}
__device__ __forceinline__ void ldm_x4_t(uint32_t* r, uint32_t a) {
    asm volatile("ldmatrix.sync.aligned.m8n8.x4.trans.shared.b16 {%0,%1,%2,%3}, [%4];"
                 : "=r"(r[0]), "=r"(r[1]), "=r"(r[2]), "=r"(r[3]) : "r"(a));
}
__device__ __forceinline__ void mma16816(float* d, const uint32_t* a,
                                         const uint32_t* b) {
    asm volatile(
        "mma.sync.aligned.m16n8k16.row.col.f32.bf16.bf16.f32 "
        "{%0,%1,%2,%3}, {%4,%5,%6,%7}, {%8,%9}, {%0,%1,%2,%3};"
        : "+f"(d[0]), "+f"(d[1]), "+f"(d[2]), "+f"(d[3])
        : "r"(a[0]), "r"(a[1]), "r"(a[2]), "r"(a[3]), "r"(b[0]), "r"(b[1]));
}
__device__ __forceinline__ void pack_hl(float f0, float f1,
                                        uint32_t& ph, uint32_t& pl) {
    __nv_bfloat16 h0 = __float2bfloat16(f0), h1 = __float2bfloat16(f1);
    __nv_bfloat162 hp = __halves2bfloat162(h0, h1);
    ph = *(uint32_t*)&hp;
    __nv_bfloat16 g0 = __float2bfloat16(f0 - __bfloat162float(h0));
    __nv_bfloat16 g1 = __float2bfloat16(f1 - __bfloat162float(h1));
    __nv_bfloat162 lp = __halves2bfloat162(g0, g1);
    pl = *(uint32_t*)&lp;
}

// GEMM smem: 2 stages x 4 arrays (Ahi,Alo,Bhi,Blo), 128 rows x 80 B
#define ROW_B    80
#define ARR_B    (128 * ROW_B)
#define STAGE_B  (4 * ARR_B)
#define GEMM_SMEM (2 * STAGE_B)         // 81920 B

// ---------------------------------------------------------------------------
// hi/lo split of X
// ---------------------------------------------------------------------------
__global__ void cvt_split_kernel(const float* __restrict__ src, int n4) {
    int i = blockIdx.x * blockDim.x + threadIdx.x;
    if (i >= n4) return;
    float4 v = ((const float4*)src)[i];
    __nv_bfloat16 h0 = __float2bfloat16(v.x);
    __nv_bfloat16 h1 = __float2bfloat16(v.y);
    __nv_bfloat16 h2 = __float2bfloat16(v.z);
    __nv_bfloat16 h3 = __float2bfloat16(v.w);
    ushort4 hv, lv;
    hv.x = *(unsigned short*)&h0; hv.y = *(unsigned short*)&h1;
    hv.z = *(unsigned short*)&h2; hv.w = *(unsigned short*)&h3;
    __nv_bfloat16 l0 = __float2bfloat16(v.x - __bfloat162float(h0));
    __nv_bfloat16 l1 = __float2bfloat16(v.y - __bfloat162float(h1));
    __nv_bfloat16 l2 = __float2bfloat16(v.z - __bfloat162float(h2));
    __nv_bfloat16 l3 = __float2bfloat16(v.w - __bfloat162float(h3));
    lv.x = *(unsigned short*)&l0; lv.y = *(unsigned short*)&l1;
    lv.z = *(unsigned short*)&l2; lv.w = *(unsigned short*)&l3;
    ((ushort4*)g_Xhi)[i] = hv;
    ((ushort4*)g_Xlo)[i] = lv;
}

// ---------------------------------------------------------------------------
// Weight transpose + hi/lo split: W[K,N] -> Wt[N,K]
// ---------------------------------------------------------------------------
__global__ void cvt_w_kernel(const float* __restrict__ Wq, const float* __restrict__ Wk,
                             const float* __restrict__ Wv, const float* __restrict__ Wo) {
    __shared__ float t[32][33];
    const int z = blockIdx.z;
    const float* W = (z == 0) ? Wq : (z == 1) ? Wk : (z == 2) ? Wv : Wo;
    const int rowoff = (z < 3) ? z * DOUT : NTOT;
    const int k0 = blockIdx.y * 32, n0 = blockIdx.x * 32;
    const int tx = threadIdx.x, ty = threadIdx.y;
#pragma unroll
    for (int i = 0; i < 4; i++)
        t[ty + i * 8][tx] = W[(size_t)(k0 + ty + i * 8) * DOUT + n0 + tx];
    __syncthreads();
#pragma unroll
    for (int i = 0; i < 4; i++) {
        const int r = ty + i * 8;
        const float x = t[tx][r];
        const __nv_bfloat16 h = __float2bfloat16(x);
        const float res = x - __bfloat162float(h);
        const size_t di = (size_t)(rowoff + n0 + r) * DIN + k0 + tx;
        g_Wthi[di] = h;
        g_Wtlo[di] = __float2bfloat16(res);
    }
}

// ---------------------------------------------------------------------------
// bf16x3 HMMA GEMM (proven).  EPI 0: hi/lo permuted store to g_{Q,K,V}{hi,lo}.
// EPI 1: fp32 store + bias -> Out.
// ---------------------------------------------------------------------------
template <int EPI>
__global__ __launch_bounds__(256, 1)
void mma_gemm_kernel(const float* __restrict__ bias, float* __restrict__ OutPlain) {
    extern __shared__ char smc[];
    const uint32_t smb = smem_u32(smc);
    const int tid = threadIdx.x, wid = tid >> 5, lane = tid & 31;
    const int warp_m = wid & 1, warp_n = wid >> 1;
    const int m0 = blockIdx.y * 128, n0 = blockIdx.x * 128;

    const __nv_bfloat16* Ahi = (EPI == 0) ? g_Xhi : g_Chi;
    const __nv_bfloat16* Alo = (EPI == 0) ? g_Xlo : g_Clo;
    const __nv_bfloat16* Bhi = (EPI == 0) ? g_Wthi : (g_Wthi + (size_t)NTOT * DIN);
    const __nv_bfloat16* Blo = (EPI == 0) ? g_Wtlo : (g_Wtlo + (size_t)NTOT * DIN);

    float acc[4][4][4];
#pragma unroll
    for (int mf = 0; mf < 4; mf++)
#pragma unroll
        for (int nf = 0; nf < 4; nf++)
#pragma unroll
            for (int j = 0; j < 4; j++) acc[mf][nf][j] = 0.f;

    auto load_chunk = [&](int ch, int st) {
#pragma unroll
        for (int t = 0; t < 4; t++) {
            const __nv_bfloat16* s = (t == 0) ? Ahi : (t == 1) ? Alo
                                   : (t == 2) ? Bhi : Blo;
            const int rb = (t < 2) ? m0 : n0;
            const uint32_t base = smb + (uint32_t)(st * STAGE_B + t * ARR_B);
#pragma unroll
            for (int j = 0; j < 2; j++) {
                const int id = tid + j * 256;
                const int row = id >> 2, c = id & 3;
                cp16(base + row * ROW_B + c * 16,
                     s + (size_t)(rb + row) * DIN + ch * KC + c * 8);
            }
        }
        CP_COMMIT();
    };

    load_chunk(0, 0);

    for (int ch = 0; ch < NCH; ch++) {
        const int st = ch & 1;
        if (ch + 1 < NCH) {
            load_chunk(ch + 1, st ^ 1);
            CP_WAIT(1);
        } else {
            CP_WAIT(0);
        }
        __syncthreads();

        const uint32_t sA = smb + st * STAGE_B;
        const uint32_t sB = sA + 2 * ARR_B;

#pragma unroll
        for (int k16 = 0; k16 < 2; k16++) {
            uint32_t ah[4][4], al[4][4], bh[4][2], bl[4][2];
#pragma unroll
            for (int f = 0; f < 4; f++) {
                const uint32_t addr = sA +
                    (warp_m * 64 + f * 16 + (lane & 15)) * ROW_B +
                    k16 * 32 + ((lane >> 4) << 4);
                ldm_x4(ah[f], addr);
                ldm_x4(al[f], addr + ARR_B);
            }
#pragma unroll
            for (int g = 0; g < 2; g++) {
                uint32_t rh[4], rl[4];
                const uint32_t addr = sB +
                    (warp_n * 32 + g * 16 + (lane & 7) + ((lane >> 4) << 3)) * ROW_B +
                    k16 * 32 + (((lane >> 3) & 1) << 4);
                ldm_x4(rh, addr);
                ldm_x4(rl, addr + ARR_B);
                bh[g * 2][0] = rh[0]; bh[g * 2][1] = rh[1];
                bh[g * 2 + 1][0] = rh[2]; bh[g * 2 + 1][1] = rh[3];
                bl[g * 2][0] = rl[0]; bl[g * 2][1] = rl[1];
                bl[g * 2 + 1][0] = rl[2]; bl[g * 2 + 1][1] = rl[3];
            }
#pragma unroll
            for (int mf = 0; mf < 4; mf++)
#pragma unroll
                for (int nf = 0; nf < 4; nf++) {
                    mma16816(acc[mf][nf], ah[mf], bh[nf]);
                    mma16816(acc[mf][nf], ah[mf], bl[nf]);
                    mma16816(acc[mf][nf], al[mf], bh[nf]);
                }
        }
        __syncthreads();
    }

#pragma unroll
    for (int mf = 0; mf < 4; mf++)
#pragma unroll
        for (int nf = 0; nf < 4; nf++) {
            const int m  = m0 + warp_m * 64 + mf * 16 + (lane >> 2);
            const int nl = warp_n * 32 + nf * 8 + (lane & 3) * 2;
            if (EPI == 0) {
                const int mat = blockIdx.x / (DOUT / 128);
                const int n = (blockIdx.x % (DOUT / 128)) * 128 + nl;
                __nv_bfloat16 *Oh, *Ol;
                if (mat == 0)      { Oh = g_Qhi; Ol = g_Qlo; }
                else if (mat == 1) { Oh = g_Khi; Ol = g_Klo; }
                else               { Oh = g_Vhi; Ol = g_Vlo; }
                const int h = n >> 6, dh = n & 63;
                const int b = m >> 11, s = m & 2047;
                const size_t i0 = (((size_t)b * NH + h) * SEQ + s) * DHD + dh;
                const size_t i1 = i0 + 8 * DHD;
                uint32_t ph, pl;
                pack_hl(acc[mf][nf][0], acc[mf][nf][1], ph, pl);
                *(uint32_t*)&Oh[i0] = ph;
                *(uint32_t*)&Ol[i0] = pl;
                pack_hl(acc[mf][nf][2], acc[mf][nf][3], ph, pl);
                *(uint32_t*)&Oh[i1] = ph;
                *(uint32_t*)&Ol[i1] = pl;
            } else {
                const int n = n0 + nl;
                float2 v0 = make_float2(acc[mf][nf][0] + bias[n],
                                        acc[mf][nf][1] + bias[n + 1]);
                float2 v1 = make_float2(acc[mf][nf][2] + bias[n],
                                        acc[mf][nf][3] + bias[n + 1]);
                *(float2*)&OutPlain[(size_t)m * DOUT + n] = v0;
                *(float2*)&OutPlain[(size_t)(m + 8) * DOUT + n] = v1;
            }
        }
}

// ---------------------------------------------------------------------------
// Tensor-core causal flash attention (bf16x3 split precision).
// CTA: 128 queries (8 warps x 16 rows), key tiles of 64, cp.async dbl buffer.
// smem layout (row stride 144 B, conflict-free ldmatrix):
//   Qhi @0 (18432), Qlo @18432; stage s @36864+s*36864:
//   Khi +0, Klo +9216, Vhi +18432, Vlo +27648.   Total 110592 B.
// Rows are DHD=64 bf16 = 128 B -> 8 x 16B chunks per row.
// ---------------------------------------------------------------------------
#define AR 144
#define ATTN_SMEM 110592

__global__ __launch_bounds__(256, 1)
void attn_mma_kernel() {
    extern __shared__ char smc[];
    const uint32_t smb = smem_u32(smc);
    const int tid = threadIdx.x, wid = tid >> 5, lane = tid & 31;
    const int qt = blockIdx.x, bh = blockIdx.y;
    const int b = bh / NH, h = bh - b * NH;
    const size_t qoff = ((size_t)bh * SEQ + qt * 128) * DHD;
    const size_t kvoff = (size_t)bh * SEQ * DHD;

    // Q tile (hi/lo) -> smem: 128 rows x 8 chunks = 1024 cp16 per array
#pragma unroll
    for (int j = 0; j < 4; j++) {
        const int id = tid + j * 256;
        const int row = id >> 3, c = id & 7;
        cp16(smb + row * AR + c * 16, g_Qhi + qoff + row * 64 + c * 8);
        cp16(smb + 18432 + row * AR + c * 16, g_Qlo + qoff + row * 64 + c * 8);
    }
    CP_COMMIT();

    auto load_kv = [&](int kt, int st) {
        const uint32_t sb = smb + 36864 + (uint32_t)st * 36864;
#pragma unroll
        for (int j = 0; j < 2; j++) {
            const int id = tid + j * 256;     // 64 rows x 8 chunks = 512
            const int row = id >> 3, c = id & 7;
            const size_t g = kvoff + (size_t)(kt * 64 + row) * 64 + c * 8;
            const uint32_t so = row * AR + c * 16;
            cp16(sb + so, g_Khi + g);
            cp16(sb + 9216 + so, g_Klo + g);
            cp16(sb + 18432 + so, g_Vhi + g);
            cp16(sb + 27648 + so, g_Vlo + g);
        }
        CP_COMMIT();
    };
    load_kv(0, 0);

    float o[8][4];
#pragma unroll
    for (int nf = 0; nf < 8; nf++)
#pragma unroll
        for (int e = 0; e < 4; e++) o[nf][e] = 0.f;
    float m0 = -3.0e38f, m1 = -3.0e38f, l0 = 0.f, l1 = 0.f;

    const int q_base = qt * 128 + wid * 16;
    const int nt = 2 * qt + 2;

    for (int kt = 0; kt < nt; kt++) {
        const int st = kt & 1;
        if (kt + 1 < nt) { load_kv(kt + 1, st ^ 1); CP_WAIT(1); }
        else             { CP_WAIT(0); }
        __syncthreads();

        const int k0 = kt * 64;
        if (k0 <= q_base) {           // warp-uniform causal skip
            const uint32_t sK = smb + 36864 + (uint32_t)st * 36864;
            const uint32_t sV = sK + 18432;

            float s[8][4];
#pragma unroll
            for (int nf = 0; nf < 8; nf++)
#pragma unroll
                for (int e = 0; e < 4; e++) s[nf][e] = 0.f;

#pragma unroll
            for (int kk = 0; kk < 4; kk++) {
                uint32_t qh[4], ql[4];
                const uint32_t qa = smb + (wid * 16 + (lane & 15)) * AR +
                                    kk * 32 + ((lane >> 4) << 4);
                ldm_x4(qh, qa);
                ldm_x4(ql, qa + 18432);
#pragma unroll
                for (int g = 0; g < 4; g++) {
                    uint32_t kh[4], kl[4];
                    const uint32_t ka = sK +
                        (g * 16 + (lane & 7) + ((lane >> 4) << 3)) * AR +
                        kk * 32 + (((lane >> 3) & 1) << 4);
                    ldm_x4(kh, ka);
                    ldm_x4(kl, ka + 9216);
                    mma16816(s[2 * g], qh, &kh[0]);
                    mma16816(s[2 * g], qh, &kl[0]);
                    mma16816(s[2 * g], ql, &kh[0]);
                    mma16816(s[2 * g + 1], qh, &kh[2]);
                    mma16816(s[2 * g + 1], qh, &kl[2]);
                    mma16816(s[2 * g + 1], ql, &kh[2]);
                }
            }

            // scale + causal mask
            const bool diag = (k0 + 63 > q_base);
#pragma unroll
            for (int nf = 0; nf < 8; nf++)
#pragma unroll
                for (int e = 0; e < 4; e++) {
                    float v = s[nf][e] * 0.125f;
                    if (diag) {
                        const int key = k0 + nf * 8 + ((lane & 3) << 1) + (e & 1);
                        const int row = q_base + (lane >> 2) + ((e & 2) ? 8 : 0);
                        if (key > row) v = -3.0e38f;
                    }
                    s[nf][e] = v;
                }

            // online softmax (rows r and r+8 per lane)
            float mx0 = -3.0e38f, mx1 = -3.0e38f;
#pragma unroll
            for (int nf = 0; nf < 8; nf++) {
                mx0 = fmaxf(mx0, fmaxf(s[nf][0], s[nf][1]));
                mx1 = fmaxf(mx1, fmaxf(s[nf][2], s[nf][3]));
            }
            mx0 = fmaxf(mx0, __shfl_xor_sync(0xffffffffu, mx0, 1));
            mx0 = fmaxf(mx0, __shfl_xor_sync(0xffffffffu, mx0, 2));
            mx1 = fmaxf(mx1, __shfl_xor_sync(0xffffffffu, mx1, 1));
            mx1 = fmaxf(mx1, __shfl_xor_sync(0xffffffffu, mx1, 2));
            const float nm0 = fmaxf(m0, mx0), nm1 = fmaxf(m1, mx1);

            float sum0 = 0.f, sum1 = 0.f;
#pragma unroll
            for (int nf = 0; nf < 8; nf++) {
                s[nf][0] = __expf(s[nf][0] - nm0);
                s[nf][1] = __expf(s[nf][1] - nm0);
                s[nf][2] = __expf(s[nf][2] - nm1);
                s[nf][3] = __expf(s[nf][3] - nm1);
                sum0 += s[nf][0] + s[nf][1];
                sum1 += s[nf][2] + s[nf][3];
            }
            sum0 += __shfl_xor_sync(0xffffffffu, sum0, 1);
            sum0 += __shfl_xor_sync(0xffffffffu, sum0, 2);
            sum1 += __shfl_xor_sync(0xffffffffu, sum1, 1);
            sum1 += __shfl_xor_sync(0xffffffffu, sum1, 2);

            const float a0 = __expf(m0 - nm0), a1 = __expf(m1 - nm1);
            l0 = l0 * a0 + sum0;
            l1 = l1 * a1 + sum1;
            m0 = nm0; m1 = nm1;
#pragma unroll
            for (int nf = 0; nf < 8; nf++) {
                o[nf][0] *= a0; o[nf][1] *= a0;
                o[nf][2] *= a1; o[nf][3] *= a1;
            }

            // O += P @ V  (P from S-frags, converted hi/lo in registers)
#pragma unroll
            for (int kk = 0; kk < 4; kk++) {
                uint32_t ph[4], pl[4];
                pack_hl(s[2 * kk][0],     s[2 * kk][1],     ph[0], pl[0]);
                pack_hl(s[2 * kk][2],     s[2 * kk][3],     ph[1], pl[1]);
                pack_hl(s[2 * kk + 1][0], s[2 * kk + 1][1], ph[2], pl[2]);
                pack_hl(s[2 * kk + 1][2], s[2 * kk + 1][3], ph[3], pl[3]);
#pragma unroll
                for (int g = 0; g < 4; g++) {
                    uint32_t vh[4], vl[4];
                    const uint32_t va = sV +
                        (kk * 16 + (lane & 7) + ((lane >> 3) & 1) * 8) * AR +
                        g * 32 + (((lane >> 4) & 1) << 4);
                    ldm_x4_t(vh, va);
                    ldm_x4_t(vl, va + 9216);
                    mma16816(o[2 * g], ph, &vh[0]);
                    mma16816(o[2 * g], ph, &vl[0]);
                    mma16816(o[2 * g], pl, &vh[0]);
                    mma16816(o[2 * g + 1], ph, &vh[2]);
                    mma16816(o[2 * g + 1], ph, &vl[2]);
                    mma16816(o[2 * g + 1], pl, &vh[2]);
                }
            }
        }
        __syncthreads();
    }

    // Epilogue: ctx hi/lo bf16, layout [b*SEQ + s][h*64 + dh]
    const float inv0 = 1.f / l0, inv1 = 1.f / l1;
    const int s0 = q_base + (lane >> 2);
#pragma unroll
    for (int nf = 0; nf < 8; nf++) {
        const int dh = nf * 8 + ((lane & 3) << 1);
        const size_t i0 = ((size_t)b * SEQ + s0) * DOUT + h * 64 + dh;
        const size_t i1 = i0 + (size_t)8 * DOUT;
        uint32_t ph, pl;
        pack_hl(o[nf][0] * inv0, o[nf][1] * inv0, ph, pl);
        *(uint32_t*)&g_Chi[i0] = ph;
        *(uint32_t*)&g_Clo[i0] = pl;
        pack_hl(o[nf][2] * inv1, o[nf][3] * inv1, ph, pl);
        *(uint32_t*)&g_Chi[i1] = ph;
        *(uint32_t*)&g_Clo[i1] = pl;
    }
}

// ---------------------------------------------------------------------------
// Launch. Inputs: [0]=x f32, [1]=mask (unused), [2..5]=Wq,Wk,Wv,Wo, [6]=bo.
// ---------------------------------------------------------------------------
extern "C" void kernel_launch(void* const* d_in, const int* in_sizes, int n_in,
                              void* d_out, int out_size) {
    const float* x  = (const float*)d_in[0];
    const float* Wq = (const float*)d_in[2];
    const float* Wk = (const float*)d_in[3];
    const float* Wv = (const float*)d_in[4];
    const float* Wo = (const float*)d_in[5];
    const float* bo = (const float*)d_in[6];
    float* out = (float*)d_out;

    cudaFuncSetAttribute(mma_gemm_kernel<0>,
                         cudaFuncAttributeMaxDynamicSharedMemorySize, GEMM_SMEM);
    cudaFuncSetAttribute(mma_gemm_kernel<1>,
                         cudaFuncAttributeMaxDynamicSharedMemorySize, GEMM_SMEM);
    cudaFuncSetAttribute(attn_mma_kernel,
                         cudaFuncAttributeMaxDynamicSharedMemorySize, ATTN_SMEM);

    // 1) Split X into hi/lo bf16
    const int n4x = MROWS * DIN / 4;
    cvt_split_kernel<<<(n4x + 255) / 256, 256>>>(x, n4x);
    // 2) Transpose + split all weights
    cvt_w_kernel<<<dim3(DOUT / 32, DIN / 32, 4), dim3(32, 8)>>>(Wq, Wk, Wv, Wo);

    // 3) Fused QKV GEMM -> bf16 hi/lo Q,K,V (permuted)
    mma_gemm_kernel<0><<<dim3(NTOT / 128, MROWS / 128), 256, GEMM_SMEM>>>(
        nullptr, nullptr);

    // 4) Tensor-core flash attention -> ctx hi/lo
    attn_mma_kernel<<<dim3(SEQ / 128, NB * NH), 256, ATTN_SMEM>>>();

    // 5) Output projection + bias
    mma_gemm_kernel<1><<<dim3(DOUT / 128, MROWS / 128), 256, GEMM_SMEM>>>(bo, out);
}